// round 14
// baseline (speedup 1.0000x reference)
#include <cuda_runtime.h>
#include <cstddef>

#define SEQ   512
#define BATCH 4096
#define INDIM 9
#define HID   64
#define OUTD  10
#define NTH   256                       // 8 warps: 0-3 L2, 4-7 L1 (hi prio)
#define BLKS  16
#define NBLK  32
#define NPH   34
#define RING  32
#define CSCALE 2.885390081777927f       // 2/ln2
#define WSCALE (-2.0f * CSCALE)

// shared memory float offsets
#define O_HIST  0                          // SEQ*HID : xw'' rows -> r2 history
#define O_XS    (O_HIST + SEQ*HID)         // SEQ*INDIM
#define O_RING  (O_XS + SEQ*INDIM)         // RING*HID  r1 ring
#define O_PIR   (O_RING + RING*HID)        // RING*HID  pI ring (pre-halved, incl base2)
#define O_R2I   (O_PIR + RING*HID)         // HID       r2(-1) init row
#define O_RS1   (O_R2I + HID)              // HID
#define O_WFC   (O_RS1 + HID)              // OUTD*HID (scaled -2)
#define O_BFC   (O_WFC + OUTD*HID)         // 16
#define SM_FLOATS (O_BFC + 16)
#define SM_BYTES  (SM_FLOATS * 4)

typedef unsigned long long ull;

__device__ __forceinline__ ull ffma2(ull a, ull b, ull c) {
    ull d; asm("fma.rn.f32x2 %0, %1, %2, %3;" : "=l"(d) : "l"(a), "l"(b), "l"(c));
    return d;
}
__device__ __forceinline__ ull fadd2(ull a, ull b) {
    ull d; asm("add.rn.f32x2 %0, %1, %2;" : "=l"(d) : "l"(a), "l"(b));
    return d;
}
__device__ __forceinline__ float f2sum(ull a) {
    float2 f = *reinterpret_cast<float2*>(&a);
    return f.x + f.y;
}
__device__ __forceinline__ ull pack2(float x, float y) {
    ull r; asm("mov.b64 %0, {%1,%2};" : "=l"(r) : "f"(x), "f"(y));
    return r;
}
// r = 1/(e^{2s}+1) with input pre-scaled by 2/ln2; tanh(s) = 1 - 2r
__device__ __forceinline__ float sig_r(float in) {
    float e, r;
    asm("ex2.approx.f32 %0, %1;" : "=f"(e) : "f"(in));
    asm("rcp.approx.f32 %0, %1;" : "=f"(r) : "f"(e + 1.0f));
    return r;
}
#define BAR1() asm volatile("bar.sync 1, 128;" ::: "memory")
#define BAR2() asm volatile("bar.sync 2, 128;" ::: "memory")

// scalar 32-long half dot, seeded: 8 LDS.128, 32 FFMA, 8 accums depth 4
__device__ __forceinline__ float sdot32(const float* __restrict__ w,
                                        const float* __restrict__ src,
                                        float seed) {
    const float4* hp = reinterpret_cast<const float4*>(src);
    float a0=seed, a1=0.f, a2=0.f, a3=0.f, a4=0.f, a5=0.f, a6=0.f, a7=0.f;
    #pragma unroll
    for (int q = 0; q < 8; q += 2) {
        float4 u = hp[q], v = hp[q+1];
        a0 = fmaf(u.x, w[4*q+0], a0);
        a1 = fmaf(u.y, w[4*q+1], a1);
        a2 = fmaf(u.z, w[4*q+2], a2);
        a3 = fmaf(u.w, w[4*q+3], a3);
        a4 = fmaf(v.x, w[4*q+4], a4);
        a5 = fmaf(v.y, w[4*q+5], a5);
        a6 = fmaf(v.z, w[4*q+6], a6);
        a7 = fmaf(v.w, w[4*q+7], a7);
    }
    return ((a0 + a1) + (a2 + a3)) + ((a4 + a5) + (a6 + a7));
}

// packed 32-long half dot (off-chain pI work)
__device__ __forceinline__ float dot32h(const ull* __restrict__ w,
                                        const float* __restrict__ src) {
    const ulonglong2* hp = reinterpret_cast<const ulonglong2*>(src);
    ull a0 = 0ull, a1 = 0ull, a2 = 0ull, a3 = 0ull;
    #pragma unroll
    for (int q = 0; q < 4; ++q) {
        ulonglong2 u = hp[2*q], v = hp[2*q+1];
        a0 = ffma2(u.x, w[4*q+0], a0);
        a1 = ffma2(u.y, w[4*q+1], a1);
        a2 = ffma2(v.x, w[4*q+2], a2);
        a3 = ffma2(v.y, w[4*q+3], a3);
    }
    return f2sum(fadd2(fadd2(a0, a1), fadd2(a2, a3)));
}

__global__ __launch_bounds__(NTH, 1)
void rnn_motion_kernel(const float* __restrict__ x,
                       const float* __restrict__ Wih0, const float* __restrict__ Whh0,
                       const float* __restrict__ bih0, const float* __restrict__ bhh0,
                       const float* __restrict__ Wih1, const float* __restrict__ Whh1,
                       const float* __restrict__ bih1, const float* __restrict__ bhh1,
                       const float* __restrict__ Wfc,  const float* __restrict__ bfc_g,
                       float* __restrict__ out)
{
    extern __shared__ float sm[];
    float* hist = sm + O_HIST;
    float* xs   = sm + O_XS;
    float* ring = sm + O_RING;
    float* pir  = sm + O_PIR;
    float* r2i  = sm + O_R2I;
    float* rs1  = sm + O_RS1;
    float* wfc  = sm + O_WFC;
    float* bfc  = sm + O_BFC;

    const int tid  = threadIdx.x;
    const int wid  = tid >> 5;
    const int lane = tid & 31;

    // ---- prologue A ----
    for (int e = tid; e < SEQ*INDIM; e += NTH) {
        int t = e / INDIM, k = e % INDIM;
        xs[e] = x[((size_t)t * BATCH + (BATCH - 1)) * INDIM + k];
    }
    for (int e = tid; e < OUTD*HID; e += NTH) wfc[e] = -2.0f * Wfc[e];
    if (tid < HID) {
        ring[(RING-1)*HID + tid] = 0.5f;    // r1(-1): h=0 <-> r=0.5
        r2i[tid]                 = 0.5f;    // r2(-1)
        const float4* p = reinterpret_cast<const float4*>(Whh0 + (size_t)tid * HID);
        float s = 0.f;
        #pragma unroll
        for (int q = 0; q < 16; ++q) { float4 v = p[q]; s += (v.x+v.y)+(v.z+v.w); }
        rs1[tid] = s;                       // rowsum(Whh0_i)
    }
    if (tid < OUTD) {                       // bfc'[o] = bfc + rowsum(Wfc_o)
        const float4* p = reinterpret_cast<const float4*>(Wfc + (size_t)tid * HID);
        float s = bfc_g[tid];
        #pragma unroll
        for (int q = 0; q < 16; ++q) { float4 v = p[q]; s += (v.x+v.y)+(v.z+v.w); }
        bfc[tid] = s;
    }
    __syncthreads();

    // ---- prologue B: xw''[t][i] = 0.5*C*(x_t.Wih0_i + b_ih0 + b_hh0 + rowsum(Whh0_i))
    //      (pre-halved: it seeds BOTH half-dots, so it enters the sum twice) ----
    {
        const int ii = tid & (HID-1);
        float wi[INDIM];
        #pragma unroll
        for (int k = 0; k < INDIM; ++k) wi[k] = 0.5f * CSCALE * Wih0[ii*INDIM + k];
        const float bb = 0.5f * CSCALE * (bih0[ii] + bhh0[ii] + rs1[ii]);
        for (int t = tid >> 6; t < SEQ; t += NTH/HID) {
            float s = bb;
            #pragma unroll
            for (int k = 0; k < INDIM; ++k) s += xs[t*INDIM + k] * wi[k];
            hist[t*HID + ii] = s;
        }
    }
    __syncthreads();

    // ==================== 2-group half-split pipelined scan ====================
    if (wid >= 4) {
        // ===== L1 group (warps 4-7, high arbiter prio): lane = (unit u, half h) =====
        const int u   = ((wid - 4) << 4) | (lane & 15);
        const int h   = lane >> 4;
        const int off = h << 5;
        float w1[32];
        {
            const float4* p = reinterpret_cast<const float4*>(Whh0 + (size_t)u * HID + off);
            #pragma unroll
            for (int q = 0; q < 8; ++q) {
                float4 v = p[q];
                w1[4*q+0] = v.x * WSCALE; w1[4*q+1] = v.y * WSCALE;
                w1[4*q+2] = v.z * WSCALE; w1[4*q+3] = v.w * WSCALE;
            }
        }
        ull wi2[16]; float rsI;
        {
            const float4* p = reinterpret_cast<const float4*>(Wih1 + (size_t)u * HID + off);
            float s = 0.f;
            #pragma unroll
            for (int q = 0; q < 8; ++q) {
                float4 v = p[q];
                s += (v.x+v.y)+(v.z+v.w);
                wi2[2*q]   = pack2(v.x*WSCALE, v.y*WSCALE);
                wi2[2*q+1] = pack2(v.z*WSCALE, v.w*WSCALE);
            }
            rsI = s + __shfl_xor_sync(0xffffffffu, s, 16);
        }
        float rsH = 0.f;
        {
            const float4* p = reinterpret_cast<const float4*>(Whh1 + (size_t)u * HID);
            #pragma unroll
            for (int q = 0; q < 16; ++q) { float4 v = p[q]; rsH += (v.x+v.y)+(v.z+v.w); }
        }
        const float b2h = 0.5f * CSCALE * (bih1[u] + bhh1[u] + rsI + rsH);

        // ---- phase 0: crit block 0, no pI ----
        {
            const float* src = ring + (RING-1)*HID;
            float*       dst = ring;
            float xwreg[BLKS];
            { const float* xwp = hist + u;
              #pragma unroll
              for (int j = 0; j < BLKS; ++j) xwreg[j] = xwp[j*HID]; }
            #pragma unroll 2
            for (int j = 0; j < BLKS; ++j) {
                float z = sdot32(w1, src + off, xwreg[j]);
                z += __shfl_xor_sync(0xffffffffu, z, 16);
                float r = sig_r(z);
                dst[u] = r;
                BAR1();
                src = dst; dst += HID;
            }
            __syncthreads();
        }
        // ---- phases 1..31: crit block m + pI block m-1 (pI after bar, off-chain) ----
        for (int m = 1; m < NBLK; ++m) {
            const int t0 = m << 4;
            const float* src = ring + ((t0 - 1) & (RING-1)) * HID;
            float*       dst = ring + (t0 & (RING-1)) * HID;
            float xwreg[BLKS];
            { const float* xwp = hist + t0*HID + u;
              #pragma unroll
              for (int j = 0; j < BLKS; ++j) xwreg[j] = xwp[j*HID]; }
            const float* rrow = ring + (((m-1) << 4) & (RING-1)) * HID + off;
            float*       pip  = pir  + (((m-1) << 4) & (RING-1)) * HID + u;
            #pragma unroll 2
            for (int j = 0; j < BLKS; ++j) {
                float z = sdot32(w1, src + off, xwreg[j]);
                z += __shfl_xor_sync(0xffffffffu, z, 16);
                float r = sig_r(z);
                dst[u] = r;
                BAR1();
                // pI for block m-1, step j: fills post-bar shadow, not on chain
                float pz = dot32h(wi2, rrow);
                pz += __shfl_xor_sync(0xffffffffu, pz, 16);
                *pip = fmaf(0.5f, pz, b2h);
                rrow += HID; pip += HID;
                src = dst; dst += HID;
            }
            __syncthreads();
        }
        // ---- phase 32: pI for block 31 only ----
        {
            const float* rrow = ring + 16*HID + off;     // block 31 -> ring rows 16..31
            float*       pip  = pir  + 16*HID + u;
            #pragma unroll 2
            for (int j = 0; j < BLKS; ++j) {
                float pz = dot32h(wi2, rrow);
                pz += __shfl_xor_sync(0xffffffffu, pz, 16);
                *pip = fmaf(0.5f, pz, b2h);
                rrow += HID; pip += HID;
            }
            __syncthreads();
        }
        // ---- phase 33 ----
        __syncthreads();
    } else {
        // ===== L2 group (warps 0-3): 2 blocks behind; seed = pir value (pre-halved) =====
        const int u   = (wid << 4) | (lane & 15);
        const int h   = lane >> 4;
        const int off = h << 5;
        float wh[32];
        {
            const float4* p = reinterpret_cast<const float4*>(Whh1 + (size_t)u * HID + off);
            #pragma unroll
            for (int q = 0; q < 8; ++q) {
                float4 v = p[q];
                wh[4*q+0] = v.x * WSCALE; wh[4*q+1] = v.y * WSCALE;
                wh[4*q+2] = v.z * WSCALE; wh[4*q+3] = v.w * WSCALE;
            }
        }
        __syncthreads();                                 // phase 0
        __syncthreads();                                 // phase 1
        for (int m = 2; m < NPH; ++m) {
            const int s0 = (m - 2) << 4;
            const float* prev = (s0 == 0) ? r2i : hist + (size_t)(s0 - 1)*HID;
            float*       cur  = hist + (size_t)s0*HID;
            const float* pip  = pir + (s0 & (RING-1)) * HID + u;
            #pragma unroll 2
            for (int j = 0; j < BLKS; ++j) {
                float seed = *pip;                       // 0.5*(pI + base2)
                float z = sdot32(wh, prev + off, seed);
                z += __shfl_xor_sync(0xffffffffu, z, 16);
                float r = sig_r(z);
                cur[u] = r;
                BAR2();
                prev = cur; cur += HID; pip += HID;
            }
            __syncthreads();
        }
    }
    __syncthreads();

    // ---- epilogue: out[t][o] = bfc'[o] + sum_k r2[t][k] * (-2*Wfc[o][k]) ----
    #pragma unroll
    for (int m = 0; m < SEQ/NTH; ++m) {
        const int t = tid + NTH * m;
        const float4* h4 = reinterpret_cast<const float4*>(hist + t*HID);
        #pragma unroll
        for (int o = 0; o < OUTD; ++o) {
            const float4* w4 = reinterpret_cast<const float4*>(wfc + o*HID);
            float s0 = bfc[o], s1 = 0.f, s2 = 0.f, s3 = 0.f;
            #pragma unroll
            for (int q = 0; q < HID/4; ++q) {
                float4 hv = h4[q], wv = w4[q];
                s0 = fmaf(hv.x, wv.x, s0);
                s1 = fmaf(hv.y, wv.y, s1);
                s2 = fmaf(hv.z, wv.z, s2);
                s3 = fmaf(hv.w, wv.w, s3);
            }
            out[t*OUTD + o] = (s0 + s1) + (s2 + s3);
        }
    }
}

extern "C" void kernel_launch(void* const* d_in, const int* in_sizes, int n_in,
                              void* d_out, int out_size) {
    (void)in_sizes; (void)n_in; (void)out_size;
    const float* x    = (const float*)d_in[0];
    const float* Wih0 = (const float*)d_in[1];
    const float* Whh0 = (const float*)d_in[2];
    const float* bih0 = (const float*)d_in[3];
    const float* bhh0 = (const float*)d_in[4];
    const float* Wih1 = (const float*)d_in[5];
    const float* Whh1 = (const float*)d_in[6];
    const float* bih1 = (const float*)d_in[7];
    const float* bhh1 = (const float*)d_in[8];
    const float* Wfc  = (const float*)d_in[9];
    const float* bfc  = (const float*)d_in[10];
    float* out = (float*)d_out;

    cudaFuncSetAttribute(rnn_motion_kernel,
                         cudaFuncAttributeMaxDynamicSharedMemorySize, SM_BYTES);
    rnn_motion_kernel<<<1, NTH, SM_BYTES>>>(
        x, Wih0, Whh0, bih0, bhh0, Wih1, Whh1, bih1, bhh1, Wfc, bfc, out);
}

// round 15
// speedup vs baseline: 1.0126x; 1.0126x over previous
#include <cuda_runtime.h>
#include <cstddef>

#define SEQ   512
#define BATCH 4096
#define INDIM 9
#define HID   64
#define OUTD  10
#define NTH   256                       // 8 warps: 0-3 pI, 4-5 L2, 6-7 L1
#define BLKS  16
#define NBLK  32
#define NPH   34
#define RING  32
#define CSCALE 2.885390081777927f       // 2/ln2
#define WSCALE (-2.0f * CSCALE)

// shared memory float offsets
#define O_HIST  0                          // SEQ*HID : xw' -> r2 history
#define O_XS    (O_HIST + SEQ*HID)         // SEQ*INDIM
#define O_RING  (O_XS + SEQ*INDIM)         // RING*HID  r1 ring
#define O_PIR   (O_RING + RING*HID)        // RING*HID  pI ring (reduced + base2)
#define O_R2    (O_PIR + RING*HID)         // 2*HID     r2 double buffer
#define O_RS1   (O_R2 + 2*HID)             // HID
#define O_WFC   (O_RS1 + HID)              // OUTD*HID (scaled -2)
#define O_BFC   (O_WFC + OUTD*HID)         // 16
#define O_FLG   (O_BFC + 16)               // 32 ints (4 used, padded)
#define SM_FLOATS (O_FLG + 32)
#define SM_BYTES  (SM_FLOATS * 4)

typedef unsigned long long ull;

__device__ __forceinline__ ull ffma2(ull a, ull b, ull c) {
    ull d; asm("fma.rn.f32x2 %0, %1, %2, %3;" : "=l"(d) : "l"(a), "l"(b), "l"(c));
    return d;
}
__device__ __forceinline__ ull fadd2(ull a, ull b) {
    ull d; asm("add.rn.f32x2 %0, %1, %2;" : "=l"(d) : "l"(a), "l"(b));
    return d;
}
__device__ __forceinline__ float f2sum(ull a) {
    float2 f = *reinterpret_cast<float2*>(&a);
    return f.x + f.y;
}
__device__ __forceinline__ ull pack2(float x, float y) {
    ull r; asm("mov.b64 %0, {%1,%2};" : "=l"(r) : "f"(x), "f"(y));
    return r;
}
// r = 1/(e^{2s}+1) with input pre-scaled by 2/ln2; tanh(s) = 1 - 2r
__device__ __forceinline__ float sig_r(float in) {
    float e, r;
    asm("ex2.approx.f32 %0, %1;" : "=f"(e) : "f"(in));
    asm("rcp.approx.f32 %0, %1;" : "=f"(r) : "f"(e + 1.0f));
    return r;
}
// release/acquire step-flag protocol (pair-internal sync, replaces bar.sync)
__device__ __forceinline__ void sig_flag(unsigned addr, int v) {
    asm volatile("st.release.cta.shared::cta.b32 [%0], %1;" :: "r"(addr), "r"(v) : "memory");
}
__device__ __forceinline__ void wait_flag(unsigned addr, int v) {
    int cur;
    do {
        asm volatile("ld.acquire.cta.shared::cta.b32 %0, [%1];"
                     : "=r"(cur) : "r"(addr) : "memory");
    } while (cur < v);
}

// full 64-dot with seeded accumulator (packed): 16 LDS.128, 32 FFMA2
__device__ __forceinline__ ull dot64_seed(const ull* __restrict__ w,
                                          const float* __restrict__ src,
                                          float seed) {
    const ulonglong2* hp = reinterpret_cast<const ulonglong2*>(src);
    ull a0 = 0ull, a1 = 0ull, a2 = 0ull;
    ull a3 = pack2(seed, 0.0f);
    #pragma unroll
    for (int q = 0; q < 8; ++q) {
        ulonglong2 u = hp[2*q], v = hp[2*q+1];
        a0 = ffma2(u.x, w[4*q+0], a0);
        a1 = ffma2(u.y, w[4*q+1], a1);
        a2 = ffma2(v.x, w[4*q+2], a2);
        a3 = ffma2(v.y, w[4*q+3], a3);
    }
    return fadd2(fadd2(a0, a1), fadd2(a2, a3));
}

// 32-long half dot for pI (separate warps, off critical path)
__device__ __forceinline__ float dot32h(const ull* __restrict__ w,
                                        const float* __restrict__ src) {
    const ulonglong2* hp = reinterpret_cast<const ulonglong2*>(src);
    ull a0 = 0ull, a1 = 0ull, a2 = 0ull, a3 = 0ull;
    #pragma unroll
    for (int q = 0; q < 4; ++q) {
        ulonglong2 u = hp[2*q], v = hp[2*q+1];
        a0 = ffma2(u.x, w[4*q+0], a0);
        a1 = ffma2(u.y, w[4*q+1], a1);
        a2 = ffma2(v.x, w[4*q+2], a2);
        a3 = ffma2(v.y, w[4*q+3], a3);
    }
    return f2sum(fadd2(fadd2(a0, a1), fadd2(a2, a3)));
}

__global__ __launch_bounds__(NTH, 1)
void rnn_motion_kernel(const float* __restrict__ x,
                       const float* __restrict__ Wih0, const float* __restrict__ Whh0,
                       const float* __restrict__ bih0, const float* __restrict__ bhh0,
                       const float* __restrict__ Wih1, const float* __restrict__ Whh1,
                       const float* __restrict__ bih1, const float* __restrict__ bhh1,
                       const float* __restrict__ Wfc,  const float* __restrict__ bfc_g,
                       float* __restrict__ out)
{
    extern __shared__ float sm[];
    float* hist = sm + O_HIST;
    float* xs   = sm + O_XS;
    float* ring = sm + O_RING;
    float* pir  = sm + O_PIR;
    float* r2b  = sm + O_R2;
    float* rs1  = sm + O_RS1;
    float* wfc  = sm + O_WFC;
    float* bfc  = sm + O_BFC;
    int*   flg  = (int*)(sm + O_FLG);   // [0],[1]: L1 warps; [2],[3]: L2 warps

    const int tid  = threadIdx.x;
    const int wid  = tid >> 5;
    const int lane = tid & 31;

    // ---- prologue A ----
    for (int e = tid; e < SEQ*INDIM; e += NTH) {
        int t = e / INDIM, k = e % INDIM;
        xs[e] = x[((size_t)t * BATCH + (BATCH - 1)) * INDIM + k];
    }
    for (int e = tid; e < OUTD*HID; e += NTH) wfc[e] = -2.0f * Wfc[e];
    if (tid < 8) flg[tid] = 0;
    if (tid < HID) {
        ring[(RING-1)*HID + tid] = 0.5f;    // r1(-1): h=0 <-> r=0.5
        r2b[HID + tid]           = 0.5f;    // r2(-1), parity 1
        const float4* p = reinterpret_cast<const float4*>(Whh0 + (size_t)tid * HID);
        float s = 0.f;
        #pragma unroll
        for (int q = 0; q < 16; ++q) { float4 v = p[q]; s += (v.x+v.y)+(v.z+v.w); }
        rs1[tid] = s;                       // rowsum(Whh0_i)
    }
    if (tid < OUTD) {                       // bfc'[o] = bfc + rowsum(Wfc_o)
        const float4* p = reinterpret_cast<const float4*>(Wfc + (size_t)tid * HID);
        float s = bfc_g[tid];
        #pragma unroll
        for (int q = 0; q < 16; ++q) { float4 v = p[q]; s += (v.x+v.y)+(v.z+v.w); }
        bfc[tid] = s;
    }
    __syncthreads();

    // ---- prologue B: xw'[t][i] = C*(x_t.Wih0_i + b_ih0 + b_hh0 + rowsum(Whh0_i)) ----
    {
        const int ii = tid & (HID-1);
        float wi[INDIM];
        #pragma unroll
        for (int k = 0; k < INDIM; ++k) wi[k] = CSCALE * Wih0[ii*INDIM + k];
        const float bb = CSCALE * (bih0[ii] + bhh0[ii] + rs1[ii]);
        for (int t = tid >> 6; t < SEQ; t += NTH/HID) {
            float s = bb;
            #pragma unroll
            for (int k = 0; k < INDIM; ++k) s += xs[t*INDIM + k] * wi[k];
            hist[t*HID + ii] = s;
        }
    }
    __syncthreads();

    // ==================== 3-stage pipelined scan (flag-synced pairs) ====================
    if (wid >= 6) {
        // ===== L1 pair (warps 6,7): unit i, 32 FFMA2/step =====
        const int w01 = wid - 6;
        const int i = (w01 << 5) | lane;
        const unsigned myf = (unsigned)__cvta_generic_to_shared(&flg[w01]);
        const unsigned paf = (unsigned)__cvta_generic_to_shared(&flg[w01 ^ 1]);
        ull w1[32];
        {
            const float4* p = reinterpret_cast<const float4*>(Whh0 + (size_t)i * HID);
            #pragma unroll
            for (int q = 0; q < 16; ++q) {
                float4 v = p[q];
                w1[2*q]   = pack2(v.x*WSCALE, v.y*WSCALE);
                w1[2*q+1] = pack2(v.z*WSCALE, v.w*WSCALE);
            }
        }
        int stepc = 1;
        for (int m = 0; m < NPH; ++m) {
            if (m < NBLK) {
                const int t0 = m * BLKS;
                const float* src = ring + ((t0 - 1) & (RING-1)) * HID;
                float*       dst = ring + (t0 & (RING-1)) * HID;
                float xwreg[BLKS];                      // block prefetch, off-chain
                {
                    const float* xwp = hist + t0*HID + i;
                    #pragma unroll
                    for (int j = 0; j < BLKS; ++j) xwreg[j] = xwp[j*HID];
                }
                #pragma unroll 2
                for (int j = 0; j < BLKS; ++j) {
                    ull s = dot64_seed(w1, src, xwreg[j]);
                    float r = sig_r(f2sum(s));
                    dst[i] = r;
                    __syncwarp();
                    if (lane == 0) sig_flag(myf, stepc);
                    wait_flag(paf, stepc);
                    ++stepc;
                    src = dst; dst += HID;
                }
            }
            __syncthreads();
        }
    } else if (wid >= 4) {
        // ===== L2 pair (warps 4,5): unit i, 32 FFMA2/step; pI+base2 seeded =====
        const int w01 = wid - 4;
        const int i = (w01 << 5) | lane;
        const unsigned myf = (unsigned)__cvta_generic_to_shared(&flg[2 + w01]);
        const unsigned paf = (unsigned)__cvta_generic_to_shared(&flg[2 + (w01 ^ 1)]);
        ull wh[32];
        {
            const float4* p = reinterpret_cast<const float4*>(Whh1 + (size_t)i * HID);
            #pragma unroll
            for (int q = 0; q < 16; ++q) {
                float4 v = p[q];
                wh[2*q]   = pack2(v.x*WSCALE, v.y*WSCALE);
                wh[2*q+1] = pack2(v.z*WSCALE, v.w*WSCALE);
            }
        }
        int stepc = 1;
        for (int m = 0; m < NPH; ++m) {
            if (m >= 2) {
                const int s0 = (m - 2) * BLKS;          // even
                const float* pip = pir + (s0 & (RING-1)) * HID + i;
                float*       hw  = hist + s0*HID + i;
                #pragma unroll 1
                for (int jj = 0; jj < BLKS/2; ++jj) {
                    {   // s even: read r2 parity 1, write parity 0
                        float pi = *pip;
                        ull a = dot64_seed(wh, r2b + HID, pi);
                        float r = sig_r(f2sum(a));
                        r2b[i] = r; *hw = r;
                        __syncwarp();
                        if (lane == 0) sig_flag(myf, stepc);
                        wait_flag(paf, stepc);
                        ++stepc;
                        pip += HID; hw += HID;
                    }
                    {   // s odd: read parity 0, write parity 1
                        float pi = *pip;
                        ull a = dot64_seed(wh, r2b, pi);
                        float r = sig_r(f2sum(a));
                        r2b[HID + i] = r; *hw = r;
                        __syncwarp();
                        if (lane == 0) sig_flag(myf, stepc);
                        wait_flag(paf, stepc);
                        ++stepc;
                        pip += HID; hw += HID;
                    }
                }
            }
            __syncthreads();
        }
    } else {
        // ===== pI quad (wid 0-3): stores Wih1.r1 + base2; 1 block behind =====
        const int u = (wid << 4) | (lane & 15);         // unit
        const int h = lane >> 4;                        // input half
        const int off = h << 5;
        ull wi2[16];
        float rsHalf;                                   // rowsum of Wih1+Whh1 half-rows
        {
            const float4* p = reinterpret_cast<const float4*>(Wih1 + (size_t)u * HID + off);
            float s = 0.f;
            #pragma unroll
            for (int q = 0; q < 8; ++q) {
                float4 v = p[q];
                s += (v.x+v.y)+(v.z+v.w);
                wi2[2*q]   = pack2(v.x*WSCALE, v.y*WSCALE);
                wi2[2*q+1] = pack2(v.z*WSCALE, v.w*WSCALE);
            }
            const float4* p2 = reinterpret_cast<const float4*>(Whh1 + (size_t)u * HID + off);
            #pragma unroll
            for (int q = 0; q < 8; ++q) {
                float4 v = p2[q];
                s += (v.x+v.y)+(v.z+v.w);
            }
            rsHalf = s;
        }
        float rsFull = rsHalf + __shfl_xor_sync(0xffffffffu, rsHalf, 16);
        const float base2 = CSCALE * (bih1[u] + bhh1[u] + rsFull);
        for (int m = 0; m < NPH; ++m) {
            if (m >= 1 && m < NBLK + 1) {
                const int s0 = (m - 1) * BLKS;
                const float* rrow = ring + (s0 & (RING-1)) * HID + off;
                float*       pip  = pir  + (s0 & (RING-1)) * HID + u;
                #pragma unroll 2
                for (int j = 0; j < BLKS; ++j) {
                    float p = dot32h(wi2, rrow);
                    p += __shfl_xor_sync(0xffffffffu, p, 16);
                    *pip = p + base2;               // both halves write same value
                    rrow += HID; pip += HID;
                }
            }
            __syncthreads();
        }
    }
    __syncthreads();

    // ---- epilogue: out[t][o] = bfc'[o] + sum_k r2[t][k] * (-2*Wfc[o][k]) ----
    #pragma unroll
    for (int m = 0; m < SEQ/NTH; ++m) {
        const int t = tid + NTH * m;
        const float4* h4 = reinterpret_cast<const float4*>(hist + t*HID);
        #pragma unroll
        for (int o = 0; o < OUTD; ++o) {
            const float4* w4 = reinterpret_cast<const float4*>(wfc + o*HID);
            float s0 = bfc[o], s1 = 0.f, s2 = 0.f, s3 = 0.f;
            #pragma unroll
            for (int q = 0; q < HID/4; ++q) {
                float4 hv = h4[q], wv = w4[q];
                s0 = fmaf(hv.x, wv.x, s0);
                s1 = fmaf(hv.y, wv.y, s1);
                s2 = fmaf(hv.z, wv.z, s2);
                s3 = fmaf(hv.w, wv.w, s3);
            }
            out[t*OUTD + o] = (s0 + s1) + (s2 + s3);
        }
    }
}

extern "C" void kernel_launch(void* const* d_in, const int* in_sizes, int n_in,
                              void* d_out, int out_size) {
    (void)in_sizes; (void)n_in; (void)out_size;
    const float* x    = (const float*)d_in[0];
    const float* Wih0 = (const float*)d_in[1];
    const float* Whh0 = (const float*)d_in[2];
    const float* bih0 = (const float*)d_in[3];
    const float* bhh0 = (const float*)d_in[4];
    const float* Wih1 = (const float*)d_in[5];
    const float* Whh1 = (const float*)d_in[6];
    const float* bih1 = (const float*)d_in[7];
    const float* bhh1 = (const float*)d_in[8];
    const float* Wfc  = (const float*)d_in[9];
    const float* bfc  = (const float*)d_in[10];
    float* out = (float*)d_out;

    cudaFuncSetAttribute(rnn_motion_kernel,
                         cudaFuncAttributeMaxDynamicSharedMemorySize, SM_BYTES);
    rnn_motion_kernel<<<1, NTH, SM_BYTES>>>(
        x, Wih0, Whh0, bih0, bhh0, Wih1, Whh1, bih1, bhh1, Wfc, bfc, out);
}

// round 16
// speedup vs baseline: 1.1126x; 1.0987x over previous
#include <cuda_runtime.h>
#include <cstddef>

#define SEQ   512
#define BATCH 4096
#define INDIM 9
#define HID   64
#define OUTD  10
#define NTH   256                       // 8 warps; L1: wid 2,6 (SMSP2), L2: wid 3,7 (SMSP3), pI: 0,1,4,5
#define BLKS  16
#define NBLK  32
#define NPH   34
#define RING  32
#define CSCALE 2.885390081777927f       // 2/ln2
#define WSCALE (-2.0f * CSCALE)

// shared memory float offsets
#define O_HIST  0                          // SEQ*HID : xw' -> r2 history
#define O_XS    (O_HIST + SEQ*HID)         // SEQ*INDIM
#define O_RING  (O_XS + SEQ*INDIM)         // RING*HID  r1 ring
#define O_PIR   (O_RING + RING*HID)        // RING*HID  pI ring (reduced + base2)
#define O_R2    (O_PIR + RING*HID)         // 2*HID     r2 double buffer
#define O_RS1   (O_R2 + 2*HID)             // HID
#define O_WFC   (O_RS1 + HID)              // OUTD*HID (scaled -2)
#define O_BFC   (O_WFC + OUTD*HID)         // 16
#define SM_FLOATS (O_BFC + 16)
#define SM_BYTES  (SM_FLOATS * 4)

typedef unsigned long long ull;

__device__ __forceinline__ ull ffma2(ull a, ull b, ull c) {
    ull d; asm("fma.rn.f32x2 %0, %1, %2, %3;" : "=l"(d) : "l"(a), "l"(b), "l"(c));
    return d;
}
__device__ __forceinline__ ull fadd2(ull a, ull b) {
    ull d; asm("add.rn.f32x2 %0, %1, %2;" : "=l"(d) : "l"(a), "l"(b));
    return d;
}
__device__ __forceinline__ float f2sum(ull a) {
    float2 f = *reinterpret_cast<float2*>(&a);
    return f.x + f.y;
}
__device__ __forceinline__ ull pack2(float x, float y) {
    ull r; asm("mov.b64 %0, {%1,%2};" : "=l"(r) : "f"(x), "f"(y));
    return r;
}
// r = 1/(e^{2s}+1) with input pre-scaled by 2/ln2; tanh(s) = 1 - 2r
__device__ __forceinline__ float sig_r(float in) {
    float e, r;
    asm("ex2.approx.f32 %0, %1;" : "=f"(e) : "f"(in));
    asm("rcp.approx.f32 %0, %1;" : "=f"(r) : "f"(e + 1.0f));
    return r;
}
// split-barrier producer/consumer: signal my STS (release), wait only on partner's arrive
__device__ __forceinline__ void bar_arrive(int id) {
    asm volatile("bar.arrive %0, 64;" :: "r"(id) : "memory");
}
__device__ __forceinline__ void bar_wait(int id) {
    asm volatile("bar.sync %0, 64;" :: "r"(id) : "memory");
}

// full 64-dot with seeded accumulator (packed): 16 LDS.128, 32 FFMA2
__device__ __forceinline__ ull dot64_seed(const ull* __restrict__ w,
                                          const float* __restrict__ src,
                                          float seed) {
    const ulonglong2* hp = reinterpret_cast<const ulonglong2*>(src);
    ull a0 = 0ull, a1 = 0ull, a2 = 0ull;
    ull a3 = pack2(seed, 0.0f);
    #pragma unroll
    for (int q = 0; q < 8; ++q) {
        ulonglong2 u = hp[2*q], v = hp[2*q+1];
        a0 = ffma2(u.x, w[4*q+0], a0);
        a1 = ffma2(u.y, w[4*q+1], a1);
        a2 = ffma2(v.x, w[4*q+2], a2);
        a3 = ffma2(v.y, w[4*q+3], a3);
    }
    return fadd2(fadd2(a0, a1), fadd2(a2, a3));
}

// 32-long half dot for pI (separate warps, off critical path)
__device__ __forceinline__ float dot32h(const ull* __restrict__ w,
                                        const float* __restrict__ src) {
    const ulonglong2* hp = reinterpret_cast<const ulonglong2*>(src);
    ull a0 = 0ull, a1 = 0ull, a2 = 0ull, a3 = 0ull;
    #pragma unroll
    for (int q = 0; q < 4; ++q) {
        ulonglong2 u = hp[2*q], v = hp[2*q+1];
        a0 = ffma2(u.x, w[4*q+0], a0);
        a1 = ffma2(u.y, w[4*q+1], a1);
        a2 = ffma2(v.x, w[4*q+2], a2);
        a3 = ffma2(v.y, w[4*q+3], a3);
    }
    return f2sum(fadd2(fadd2(a0, a1), fadd2(a2, a3)));
}

__global__ __launch_bounds__(NTH, 1)
void rnn_motion_kernel(const float* __restrict__ x,
                       const float* __restrict__ Wih0, const float* __restrict__ Whh0,
                       const float* __restrict__ bih0, const float* __restrict__ bhh0,
                       const float* __restrict__ Wih1, const float* __restrict__ Whh1,
                       const float* __restrict__ bih1, const float* __restrict__ bhh1,
                       const float* __restrict__ Wfc,  const float* __restrict__ bfc_g,
                       float* __restrict__ out)
{
    extern __shared__ float sm[];
    float* hist = sm + O_HIST;
    float* xs   = sm + O_XS;
    float* ring = sm + O_RING;
    float* pir  = sm + O_PIR;
    float* r2b  = sm + O_R2;
    float* rs1  = sm + O_RS1;
    float* wfc  = sm + O_WFC;
    float* bfc  = sm + O_BFC;

    const int tid  = threadIdx.x;
    const int wid  = tid >> 5;
    const int lane = tid & 31;

    // role: L1 = wid 2,6 (same SMSP 2); L2 = wid 3,7 (SMSP 3); pI = wid 0,1,4,5
    const int role = (wid & 3) >= 2 ? ((wid & 3) - 1) : 0;   // 0=pI, 1=L1, 2=L2
    const int half = wid >> 2;                                // 0 or 1 for L1/L2 pairs

    // ---- prologue A ----
    for (int e = tid; e < SEQ*INDIM; e += NTH) {
        int t = e / INDIM, k = e % INDIM;
        xs[e] = x[((size_t)t * BATCH + (BATCH - 1)) * INDIM + k];
    }
    for (int e = tid; e < OUTD*HID; e += NTH) wfc[e] = -2.0f * Wfc[e];
    if (tid < HID) {
        ring[(RING-1)*HID + tid] = 0.5f;    // r1(-1): h=0 <-> r=0.5
        r2b[HID + tid]           = 0.5f;    // r2(-1), parity 1
        const float4* p = reinterpret_cast<const float4*>(Whh0 + (size_t)tid * HID);
        float s = 0.f;
        #pragma unroll
        for (int q = 0; q < 16; ++q) { float4 v = p[q]; s += (v.x+v.y)+(v.z+v.w); }
        rs1[tid] = s;                       // rowsum(Whh0_i)
    }
    if (tid < OUTD) {                       // bfc'[o] = bfc + rowsum(Wfc_o)
        const float4* p = reinterpret_cast<const float4*>(Wfc + (size_t)tid * HID);
        float s = bfc_g[tid];
        #pragma unroll
        for (int q = 0; q < 16; ++q) { float4 v = p[q]; s += (v.x+v.y)+(v.z+v.w); }
        bfc[tid] = s;
    }
    __syncthreads();

    // ---- prologue B: xw'[t][i] = C*(x_t.Wih0_i + b_ih0 + b_hh0 + rowsum(Whh0_i)) ----
    {
        const int ii = tid & (HID-1);
        float wi[INDIM];
        #pragma unroll
        for (int k = 0; k < INDIM; ++k) wi[k] = CSCALE * Wih0[ii*INDIM + k];
        const float bb = CSCALE * (bih0[ii] + bhh0[ii] + rs1[ii]);
        for (int t = tid >> 6; t < SEQ; t += NTH/HID) {
            float s = bb;
            #pragma unroll
            for (int k = 0; k < INDIM; ++k) s += xs[t*INDIM + k] * wi[k];
            hist[t*HID + ii] = s;
        }
    }
    __syncthreads();

    // ==================== 3-stage pipelined scan (split barriers) ====================
    if (role == 1) {
        // ===== L1 pair (wid 2,6; same SMSP): unit i, 32 FFMA2/step =====
        const int i = (half << 5) | lane;
        const int barA = 1 + half;          // arrive id: half0->1, half1->2
        const int barW = 2 - half;          // wait id:   half0->2, half1->1
        ull w1[32];
        {
            const float4* p = reinterpret_cast<const float4*>(Whh0 + (size_t)i * HID);
            #pragma unroll
            for (int q = 0; q < 16; ++q) {
                float4 v = p[q];
                w1[2*q]   = pack2(v.x*WSCALE, v.y*WSCALE);
                w1[2*q+1] = pack2(v.z*WSCALE, v.w*WSCALE);
            }
        }
        for (int m = 0; m < NPH; ++m) {
            if (m < NBLK) {
                const int t0 = m * BLKS;
                const float* src = ring + ((t0 - 1) & (RING-1)) * HID;
                float*       dst = ring + (t0 & (RING-1)) * HID;
                float xwreg[BLKS];                      // block prefetch, off-chain
                {
                    const float* xwp = hist + t0*HID + i;
                    #pragma unroll
                    for (int j = 0; j < BLKS; ++j) xwreg[j] = xwp[j*HID];
                }
                #pragma unroll 2
                for (int j = 0; j < BLKS; ++j) {
                    ull s = dot64_seed(w1, src, xwreg[j]);
                    float r = sig_r(f2sum(s));
                    dst[i] = r;
                    bar_arrive(barA);                   // release my STS, non-blocking
                    bar_wait(barW);                     // gate only on partner's arrive
                    src = dst; dst += HID;
                }
            }
            __syncthreads();
        }
    } else if (role == 2) {
        // ===== L2 pair (wid 3,7; same SMSP): unit i, pI+base2 seeded =====
        const int i = (half << 5) | lane;
        const int barA = 3 + half;          // half0->3, half1->4
        const int barW = 4 - half;          // half0->4, half1->3
        ull wh[32];
        {
            const float4* p = reinterpret_cast<const float4*>(Whh1 + (size_t)i * HID);
            #pragma unroll
            for (int q = 0; q < 16; ++q) {
                float4 v = p[q];
                wh[2*q]   = pack2(v.x*WSCALE, v.y*WSCALE);
                wh[2*q+1] = pack2(v.z*WSCALE, v.w*WSCALE);
            }
        }
        for (int m = 0; m < NPH; ++m) {
            if (m >= 2) {
                const int s0 = (m - 2) * BLKS;          // even
                const float* pip = pir + (s0 & (RING-1)) * HID + i;
                float*       hw  = hist + s0*HID + i;
                #pragma unroll 1
                for (int jj = 0; jj < BLKS/2; ++jj) {
                    {   // s even: read r2 parity 1, write parity 0
                        float pi = *pip;
                        ull a = dot64_seed(wh, r2b + HID, pi);
                        float r = sig_r(f2sum(a));
                        r2b[i] = r; *hw = r;
                        bar_arrive(barA);
                        bar_wait(barW);
                        pip += HID; hw += HID;
                    }
                    {   // s odd: read parity 0, write parity 1
                        float pi = *pip;
                        ull a = dot64_seed(wh, r2b, pi);
                        float r = sig_r(f2sum(a));
                        r2b[HID + i] = r; *hw = r;
                        bar_arrive(barA);
                        bar_wait(barW);
                        pip += HID; hw += HID;
                    }
                }
            }
            __syncthreads();
        }
    } else {
        // ===== pI quad (wid 0,1,4,5): stores Wih1.r1 + base2; 1 block behind =====
        const int pw = (wid & 1) | ((wid >> 2) << 1);   // 0,1,4,5 -> 0,1,2,3
        const int u = (pw << 4) | (lane & 15);          // unit
        const int h = lane >> 4;                        // input half
        const int off = h << 5;
        ull wi2[16];
        float rsHalf;                                   // rowsum of Wih1+Whh1 half-rows
        {
            const float4* p = reinterpret_cast<const float4*>(Wih1 + (size_t)u * HID + off);
            float s = 0.f;
            #pragma unroll
            for (int q = 0; q < 8; ++q) {
                float4 v = p[q];
                s += (v.x+v.y)+(v.z+v.w);
                wi2[2*q]   = pack2(v.x*WSCALE, v.y*WSCALE);
                wi2[2*q+1] = pack2(v.z*WSCALE, v.w*WSCALE);
            }
            const float4* p2 = reinterpret_cast<const float4*>(Whh1 + (size_t)u * HID + off);
            #pragma unroll
            for (int q = 0; q < 8; ++q) {
                float4 v = p2[q];
                s += (v.x+v.y)+(v.z+v.w);
            }
            rsHalf = s;
        }
        float rsFull = rsHalf + __shfl_xor_sync(0xffffffffu, rsHalf, 16);
        const float base2 = CSCALE * (bih1[u] + bhh1[u] + rsFull);
        for (int m = 0; m < NPH; ++m) {
            if (m >= 1 && m < NBLK + 1) {
                const int s0 = (m - 1) * BLKS;
                const float* rrow = ring + (s0 & (RING-1)) * HID + off;
                float*       pip  = pir  + (s0 & (RING-1)) * HID + u;
                #pragma unroll 2
                for (int j = 0; j < BLKS; ++j) {
                    float p = dot32h(wi2, rrow);
                    p += __shfl_xor_sync(0xffffffffu, p, 16);
                    *pip = p + base2;               // both halves write same value
                    rrow += HID; pip += HID;
                }
            }
            __syncthreads();
        }
    }
    __syncthreads();

    // ---- epilogue: out[t][o] = bfc'[o] + sum_k r2[t][k] * (-2*Wfc[o][k]) ----
    #pragma unroll
    for (int m = 0; m < SEQ/NTH; ++m) {
        const int t = tid + NTH * m;
        const float4* h4 = reinterpret_cast<const float4*>(hist + t*HID);
        #pragma unroll
        for (int o = 0; o < OUTD; ++o) {
            const float4* w4 = reinterpret_cast<const float4*>(wfc + o*HID);
            float s0 = bfc[o], s1 = 0.f, s2 = 0.f, s3 = 0.f;
            #pragma unroll
            for (int q = 0; q < HID/4; ++q) {
                float4 hv = h4[q], wv = w4[q];
                s0 = fmaf(hv.x, wv.x, s0);
                s1 = fmaf(hv.y, wv.y, s1);
                s2 = fmaf(hv.z, wv.z, s2);
                s3 = fmaf(hv.w, wv.w, s3);
            }
            out[t*OUTD + o] = (s0 + s1) + (s2 + s3);
        }
    }
}

extern "C" void kernel_launch(void* const* d_in, const int* in_sizes, int n_in,
                              void* d_out, int out_size) {
    (void)in_sizes; (void)n_in; (void)out_size;
    const float* x    = (const float*)d_in[0];
    const float* Wih0 = (const float*)d_in[1];
    const float* Whh0 = (const float*)d_in[2];
    const float* bih0 = (const float*)d_in[3];
    const float* bhh0 = (const float*)d_in[4];
    const float* Wih1 = (const float*)d_in[5];
    const float* Whh1 = (const float*)d_in[6];
    const float* bih1 = (const float*)d_in[7];
    const float* bhh1 = (const float*)d_in[8];
    const float* Wfc  = (const float*)d_in[9];
    const float* bfc  = (const float*)d_in[10];
    float* out = (float*)d_out;

    cudaFuncSetAttribute(rnn_motion_kernel,
                         cudaFuncAttributeMaxDynamicSharedMemorySize, SM_BYTES);
    rnn_motion_kernel<<<1, NTH, SM_BYTES>>>(
        x, Wih0, Whh0, bih0, bhh0, Wih1, Whh1, bih1, bhh1, Wfc, bfc, out);
}

// round 17
// speedup vs baseline: 1.3617x; 1.2239x over previous
#include <cuda_runtime.h>
#include <cstddef>

#define SEQ   512
#define BATCH 4096
#define INDIM 9
#define HID   64
#define OUTD  10
#define NTH   256                       // 8 warps: 0-3 pI, 4-5 L2, 6-7 L1
#define BLKS  32                        // steps per phase (was 16)
#define NBLK  (SEQ/BLKS)                // 16
#define NPH   (NBLK + 2)                // 18 phases
#define RING  64                        // ring rows (2 blocks)
#define CSCALE 2.885390081777927f       // 2/ln2
#define WSCALE (-2.0f * CSCALE)

// shared memory float offsets
#define O_HIST  0                          // SEQ*HID : xw' -> r2 history
#define O_XS    (O_HIST + SEQ*HID)         // SEQ*INDIM
#define O_RING  (O_XS + SEQ*INDIM)         // RING*HID  r1 ring
#define O_PIR   (O_RING + RING*HID)        // RING*HID  pI ring (reduced + base2)
#define O_R2    (O_PIR + RING*HID)         // 2*HID     r2 double buffer
#define O_RS1   (O_R2 + 2*HID)             // HID
#define O_WFC   (O_RS1 + HID)              // OUTD*HID (scaled -2)
#define O_BFC   (O_WFC + OUTD*HID)         // 16
#define SM_FLOATS (O_BFC + 16)
#define SM_BYTES  (SM_FLOATS * 4)          // ~186 KB

typedef unsigned long long ull;

__device__ __forceinline__ ull ffma2(ull a, ull b, ull c) {
    ull d; asm("fma.rn.f32x2 %0, %1, %2, %3;" : "=l"(d) : "l"(a), "l"(b), "l"(c));
    return d;
}
__device__ __forceinline__ ull fadd2(ull a, ull b) {
    ull d; asm("add.rn.f32x2 %0, %1, %2;" : "=l"(d) : "l"(a), "l"(b));
    return d;
}
__device__ __forceinline__ float f2sum(ull a) {
    float2 f = *reinterpret_cast<float2*>(&a);
    return f.x + f.y;
}
__device__ __forceinline__ ull pack2(float x, float y) {
    ull r; asm("mov.b64 %0, {%1,%2};" : "=l"(r) : "f"(x), "f"(y));
    return r;
}
// r = 1/(e^{2s}+1) with input pre-scaled by 2/ln2; tanh(s) = 1 - 2r
__device__ __forceinline__ float sig_r(float in) {
    float e, r;
    asm("ex2.approx.f32 %0, %1;" : "=f"(e) : "f"(in));
    asm("rcp.approx.f32 %0, %1;" : "=f"(r) : "f"(e + 1.0f));
    return r;
}
#define BAR_L1() asm volatile("bar.sync 1, 64;" ::: "memory")
#define BAR_L2() asm volatile("bar.sync 2, 64;" ::: "memory")

// full 64-dot, packed FFMA2, SCALAR reduction tree (3 levels x 4 cyc)
__device__ __forceinline__ float dot64s(const ull* __restrict__ w,
                                        const float* __restrict__ src,
                                        float seed) {
    const ulonglong2* hp = reinterpret_cast<const ulonglong2*>(src);
    ull a0 = 0ull, a1 = 0ull, a2 = 0ull;
    ull a3 = pack2(seed, 0.0f);
    #pragma unroll
    for (int q = 0; q < 8; ++q) {
        ulonglong2 u = hp[2*q], v = hp[2*q+1];
        a0 = ffma2(u.x, w[4*q+0], a0);
        a1 = ffma2(u.y, w[4*q+1], a1);
        a2 = ffma2(v.x, w[4*q+2], a2);
        a3 = ffma2(v.y, w[4*q+3], a3);
    }
    float2 f0 = *reinterpret_cast<float2*>(&a0);
    float2 f1 = *reinterpret_cast<float2*>(&a1);
    float2 f2 = *reinterpret_cast<float2*>(&a2);
    float2 f3 = *reinterpret_cast<float2*>(&a3);
    return ((f0.x + f0.y) + (f1.x + f1.y)) + ((f2.x + f2.y) + (f3.x + f3.y));
}

// 32-long half dot for pI (separate warps, off critical path)
__device__ __forceinline__ float dot32h(const ull* __restrict__ w,
                                        const float* __restrict__ src) {
    const ulonglong2* hp = reinterpret_cast<const ulonglong2*>(src);
    ull a0 = 0ull, a1 = 0ull, a2 = 0ull, a3 = 0ull;
    #pragma unroll
    for (int q = 0; q < 4; ++q) {
        ulonglong2 u = hp[2*q], v = hp[2*q+1];
        a0 = ffma2(u.x, w[4*q+0], a0);
        a1 = ffma2(u.y, w[4*q+1], a1);
        a2 = ffma2(v.x, w[4*q+2], a2);
        a3 = ffma2(v.y, w[4*q+3], a3);
    }
    return f2sum(fadd2(fadd2(a0, a1), fadd2(a2, a3)));
}

__global__ __launch_bounds__(NTH, 1)
void rnn_motion_kernel(const float* __restrict__ x,
                       const float* __restrict__ Wih0, const float* __restrict__ Whh0,
                       const float* __restrict__ bih0, const float* __restrict__ bhh0,
                       const float* __restrict__ Wih1, const float* __restrict__ Whh1,
                       const float* __restrict__ bih1, const float* __restrict__ bhh1,
                       const float* __restrict__ Wfc,  const float* __restrict__ bfc_g,
                       float* __restrict__ out)
{
    extern __shared__ float sm[];
    float* hist = sm + O_HIST;
    float* xs   = sm + O_XS;
    float* ring = sm + O_RING;
    float* pir  = sm + O_PIR;
    float* r2b  = sm + O_R2;
    float* rs1  = sm + O_RS1;
    float* wfc  = sm + O_WFC;
    float* bfc  = sm + O_BFC;

    const int tid  = threadIdx.x;
    const int wid  = tid >> 5;
    const int lane = tid & 31;

    // ---- prologue A ----
    for (int e = tid; e < SEQ*INDIM; e += NTH) {
        int t = e / INDIM, k = e % INDIM;
        xs[e] = x[((size_t)t * BATCH + (BATCH - 1)) * INDIM + k];
    }
    for (int e = tid; e < OUTD*HID; e += NTH) wfc[e] = -2.0f * Wfc[e];
    if (tid < HID) {
        ring[(RING-1)*HID + tid] = 0.5f;    // r1(-1): h=0 <-> r=0.5
        r2b[HID + tid]           = 0.5f;    // r2(-1), parity 1
        const float4* p = reinterpret_cast<const float4*>(Whh0 + (size_t)tid * HID);
        float s = 0.f;
        #pragma unroll
        for (int q = 0; q < 16; ++q) { float4 v = p[q]; s += (v.x+v.y)+(v.z+v.w); }
        rs1[tid] = s;                       // rowsum(Whh0_i)
    }
    if (tid < OUTD) {                       // bfc'[o] = bfc + rowsum(Wfc_o)
        const float4* p = reinterpret_cast<const float4*>(Wfc + (size_t)tid * HID);
        float s = bfc_g[tid];
        #pragma unroll
        for (int q = 0; q < 16; ++q) { float4 v = p[q]; s += (v.x+v.y)+(v.z+v.w); }
        bfc[tid] = s;
    }
    __syncthreads();

    // ---- prologue B: xw'[t][i] = C*(x_t.Wih0_i + b_ih0 + b_hh0 + rowsum(Whh0_i)) ----
    {
        const int ii = tid & (HID-1);
        float wi[INDIM];
        #pragma unroll
        for (int k = 0; k < INDIM; ++k) wi[k] = CSCALE * Wih0[ii*INDIM + k];
        const float bb = CSCALE * (bih0[ii] + bhh0[ii] + rs1[ii]);
        for (int t = tid >> 6; t < SEQ; t += NTH/HID) {
            float s = bb;
            #pragma unroll
            for (int k = 0; k < INDIM; ++k) s += xs[t*INDIM + k] * wi[k];
            hist[t*HID + ii] = s;
        }
    }
    __syncthreads();

    // ==================== 3-stage pipelined scan ====================
    if (wid >= 6) {
        // ===== L1 pair (warps 6,7): unit i, 32 FFMA2/step =====
        const int i = ((wid - 6) << 5) | lane;
        ull w1[32];
        {
            const float4* p = reinterpret_cast<const float4*>(Whh0 + (size_t)i * HID);
            #pragma unroll
            for (int q = 0; q < 16; ++q) {
                float4 v = p[q];
                w1[2*q]   = pack2(v.x*WSCALE, v.y*WSCALE);
                w1[2*q+1] = pack2(v.z*WSCALE, v.w*WSCALE);
            }
        }
        for (int m = 0; m < NPH; ++m) {
            if (m < NBLK) {
                const int t0 = m * BLKS;
                const float* src = ring + ((t0 - 1) & (RING-1)) * HID;
                float*       dst = ring + (t0 & (RING-1)) * HID;
                const float* xwp = hist + t0*HID + i;
                #pragma unroll 2
                for (int j = 0; j < BLKS; ++j) {
                    float xw = *xwp;                    // issued first, covered by dot
                    float s = dot64s(w1, src, xw);
                    float r = sig_r(s);
                    dst[i] = r;
                    BAR_L1();
                    src = dst; dst += HID; xwp += HID;
                }
            }
            __syncthreads();
        }
    } else if (wid >= 4) {
        // ===== L2 pair (warps 4,5): unit i, pI+base2 seeded =====
        const int i = ((wid - 4) << 5) | lane;
        ull wh[32];
        {
            const float4* p = reinterpret_cast<const float4*>(Whh1 + (size_t)i * HID);
            #pragma unroll
            for (int q = 0; q < 16; ++q) {
                float4 v = p[q];
                wh[2*q]   = pack2(v.x*WSCALE, v.y*WSCALE);
                wh[2*q+1] = pack2(v.z*WSCALE, v.w*WSCALE);
            }
        }
        for (int m = 0; m < NPH; ++m) {
            if (m >= 2) {
                const int s0 = (m - 2) * BLKS;          // even
                const float* pip = pir + (s0 & (RING-1)) * HID + i;
                float*       hw  = hist + s0*HID + i;
                #pragma unroll 1
                for (int jj = 0; jj < BLKS/2; ++jj) {
                    {   // s even: read r2 parity 1, write parity 0
                        float pi = *pip;
                        float a = dot64s(wh, r2b + HID, pi);
                        float r = sig_r(a);
                        r2b[i] = r; *hw = r;
                        BAR_L2();
                        pip += HID; hw += HID;
                    }
                    {   // s odd: read parity 0, write parity 1
                        float pi = *pip;
                        float a = dot64s(wh, r2b, pi);
                        float r = sig_r(a);
                        r2b[HID + i] = r; *hw = r;
                        BAR_L2();
                        pip += HID; hw += HID;
                    }
                }
            }
            __syncthreads();
        }
    } else {
        // ===== pI quad (wid 0-3): stores Wih1.r1 + base2; 1 block behind =====
        const int u = (wid << 4) | (lane & 15);         // unit
        const int h = lane >> 4;                        // input half
        const int off = h << 5;
        ull wi2[16];
        float rsHalf;                                   // rowsum of Wih1+Whh1 half-rows
        {
            const float4* p = reinterpret_cast<const float4*>(Wih1 + (size_t)u * HID + off);
            float s = 0.f;
            #pragma unroll
            for (int q = 0; q < 8; ++q) {
                float4 v = p[q];
                s += (v.x+v.y)+(v.z+v.w);
                wi2[2*q]   = pack2(v.x*WSCALE, v.y*WSCALE);
                wi2[2*q+1] = pack2(v.z*WSCALE, v.w*WSCALE);
            }
            const float4* p2 = reinterpret_cast<const float4*>(Whh1 + (size_t)u * HID + off);
            #pragma unroll
            for (int q = 0; q < 8; ++q) {
                float4 v = p2[q];
                s += (v.x+v.y)+(v.z+v.w);
            }
            rsHalf = s;
        }
        float rsFull = rsHalf + __shfl_xor_sync(0xffffffffu, rsHalf, 16);
        const float base2 = CSCALE * (bih1[u] + bhh1[u] + rsFull);
        for (int m = 0; m < NPH; ++m) {
            if (m >= 1 && m < NBLK + 1) {
                const int s0 = (m - 1) * BLKS;
                const float* rrow = ring + (s0 & (RING-1)) * HID + off;
                float*       pip  = pir  + (s0 & (RING-1)) * HID + u;
                #pragma unroll 2
                for (int j = 0; j < BLKS; ++j) {
                    float p = dot32h(wi2, rrow);
                    p += __shfl_xor_sync(0xffffffffu, p, 16);
                    *pip = p + base2;               // both halves write same value
                    rrow += HID; pip += HID;
                }
            }
            __syncthreads();
        }
    }
    __syncthreads();

    // ---- epilogue: out[t][o] = bfc'[o] + sum_k r2[t][k] * (-2*Wfc[o][k]) ----
    #pragma unroll
    for (int m = 0; m < SEQ/NTH; ++m) {
        const int t = tid + NTH * m;
        const float4* h4 = reinterpret_cast<const float4*>(hist + t*HID);
        #pragma unroll
        for (int o = 0; o < OUTD; ++o) {
            const float4* w4 = reinterpret_cast<const float4*>(wfc + o*HID);
            float s0 = bfc[o], s1 = 0.f, s2 = 0.f, s3 = 0.f;
            #pragma unroll
            for (int q = 0; q < HID/4; ++q) {
                float4 hv = h4[q], wv = w4[q];
                s0 = fmaf(hv.x, wv.x, s0);
                s1 = fmaf(hv.y, wv.y, s1);
                s2 = fmaf(hv.z, wv.z, s2);
                s3 = fmaf(hv.w, wv.w, s3);
            }
            out[t*OUTD + o] = (s0 + s1) + (s2 + s3);
        }
    }
}

extern "C" void kernel_launch(void* const* d_in, const int* in_sizes, int n_in,
                              void* d_out, int out_size) {
    (void)in_sizes; (void)n_in; (void)out_size;
    const float* x    = (const float*)d_in[0];
    const float* Wih0 = (const float*)d_in[1];
    const float* Whh0 = (const float*)d_in[2];
    const float* bih0 = (const float*)d_in[3];
    const float* bhh0 = (const float*)d_in[4];
    const float* Wih1 = (const float*)d_in[5];
    const float* Whh1 = (const float*)d_in[6];
    const float* bih1 = (const float*)d_in[7];
    const float* bhh1 = (const float*)d_in[8];
    const float* Wfc  = (const float*)d_in[9];
    const float* bfc  = (const float*)d_in[10];
    float* out = (float*)d_out;

    cudaFuncSetAttribute(rnn_motion_kernel,
                         cudaFuncAttributeMaxDynamicSharedMemorySize, SM_BYTES);
    rnn_motion_kernel<<<1, NTH, SM_BYTES>>>(
        x, Wih0, Whh0, bih0, bhh0, Wih1, Whh1, bih1, bhh1, Wfc, bfc, out);
}